// round 5
// baseline (speedup 1.0000x reference)
#include <cuda_runtime.h>
#include <cuda_bf16.h>
#include <cstdint>

#define MAX_D 8192
__device__ __align__(128) float g_mask[MAX_D];
__device__ unsigned int g_done;   // reset to 0 via cudaMemsetAsync each call

// ---------------------------------------------------------------------------
// Fused kernel.
// Blocks [0, maskBlocks): compute exact top-k channel mask (lax.top_k tie
// semantics: rank(d) = #{j: imp[j]>imp[d]} + #{j<d: imp[j]==imp[d]}), publish
// g_mask, fence, count up g_done.
// ALL blocks: load their x tile first (overlaps the mask phase), then spin on
// g_done (acquire), then y = x + m*(poly(x)-x), streaming store.
// Requires: maskBlocks = D/16 <= gridDim.x, D <= 4096, D % 256 == 0.
// ---------------------------------------------------------------------------
__global__ void __launch_bounds__(256)
fused_kernel(const float4* __restrict__ x,
             const float* __restrict__ coeffs,
             float4* __restrict__ out,
             int n4, unsigned int d4_mask,
             const float* __restrict__ imp, int D, int keep, int maskBlocks) {
    __shared__ float s_imp[4096];      // 16 KB (only mask blocks populate)
    __shared__ int   s_part[16][17];

    int tid = threadIdx.x;
    int i = blockIdx.x * blockDim.x + tid;
    bool active = (i < n4);

    // ---- Phase A: issue streaming loads early (independent of mask) ----
    float4 xv = make_float4(0.f, 0.f, 0.f, 0.f);
    if (active) xv = __ldcs(&x[i]);
    float c0 = __ldg(&coeffs[0]);
    float c1 = __ldg(&coeffs[1]);
    float c2 = __ldg(&coeffs[2]);

    float px = xv.x * fmaf(xv.x, fmaf(xv.x, c2, c1), c0);
    float py = xv.y * fmaf(xv.y, fmaf(xv.y, c2, c1), c0);
    float pz = xv.z * fmaf(xv.z, fmaf(xv.z, c2, c1), c0);
    float pw = xv.w * fmaf(xv.w, fmaf(xv.w, c2, c1), c0);

    // ---- Phase B: mask computation on the first maskBlocks blocks ----
    if ((int)blockIdx.x < maskBlocks) {
        for (int j = tid; j < D; j += blockDim.x) s_imp[j] = imp[j];
        __syncthreads();

        int chIdx = tid & 15;              // channel within block
        int sl    = tid >> 4;              // j-slice (0..15)
        int d     = blockIdx.x * 16 + chIdx;
        float v   = s_imp[d];

        int chunk = D >> 4;                // 256 @ D=4096
        int base  = sl * chunk;
        int cnt = 0;
        #pragma unroll 8
        for (int j = 0; j < chunk; j++) {
            int jj = base + j;
            float u = s_imp[jj];
            cnt += (u > v) ? 1 : ((u == v && jj < d) ? 1 : 0);
        }
        s_part[sl][chIdx] = cnt;
        __syncthreads();

        if (tid < 16) {
            int r = 0;
            #pragma unroll
            for (int s = 0; s < 16; s++) r += s_part[s][tid];
            g_mask[blockIdx.x * 16 + tid] = (r < keep) ? 1.0f : 0.0f;
        }
        __threadfence();                   // publish g_mask before counting
        __syncthreads();
        if (tid == 0) atomicAdd(&g_done, 1u);
    }

    // ---- Phase C: wait for mask (device-side, acquire) ----
    if (tid == 0) {
        unsigned int v;
        do {
            asm volatile("ld.acquire.gpu.u32 %0, [%1];"
                         : "=r"(v) : "l"(&g_done) : "memory");
            if ((int)v >= maskBlocks) break;
            __nanosleep(32);
        } while (true);
    }
    __syncthreads();

    // ---- Phase D: finalize + streaming store ----
    if (active) {
        const float4* m4 = reinterpret_cast<const float4*>(g_mask);
        float4 mv = m4[i & d4_mask];
        float4 r;
        r.x = fmaf(mv.x, px - xv.x, xv.x);
        r.y = fmaf(mv.y, py - xv.y, xv.y);
        r.z = fmaf(mv.z, pz - xv.z, xv.z);
        r.w = fmaf(mv.w, pw - xv.w, xv.w);
        __stcs(&out[i], r);
    }
}

// ---------------------------------------------------------------------------
// Fallback path (two kernels) — only used if shape assumptions fail.
// ---------------------------------------------------------------------------
__global__ void mask_kernel_fb(const float* __restrict__ imp, int D, int keep) {
    int d = blockIdx.x * blockDim.x + threadIdx.x;
    if (d >= D) return;
    float v = imp[d];
    int cnt = 0;
    for (int j = 0; j < D; j++) {
        float u = imp[j];
        cnt += (u > v) ? 1 : ((u == v && j < d) ? 1 : 0);
    }
    g_mask[d] = (cnt < keep) ? 1.0f : 0.0f;
}

__global__ void poly_kernel_fb(const float* __restrict__ x,
                               const float* __restrict__ coeffs,
                               float* __restrict__ out, int n, int D) {
    int i = blockIdx.x * blockDim.x + threadIdx.x;
    if (i >= n) return;
    float c0 = coeffs[0], c1 = coeffs[1], c2 = coeffs[2];
    float xv = x[i];
    float m = g_mask[i % D];
    float p = xv * fmaf(xv, fmaf(xv, c2, c1), c0);
    out[i] = fmaf(m, p - xv, xv);
}

extern "C" void kernel_launch(void* const* d_in, const int* in_sizes, int n_in,
                              void* d_out, int out_size) {
    const float* x    = (const float*)d_in[0];   // (B, T, D) fp32
    const float* coef = (const float*)d_in[1];   // (3,) fp32
    const float* imp  = (const float*)d_in[2];   // (D,) fp32

    int D    = in_sizes[2];                      // 4096
    int keep = (int)(D * 0.5);
    if (keep < 1) keep = 1;
    int n    = in_sizes[0];                      // B*T*D

    int n4 = n / 4;
    int threads = 256;
    int blocks  = (n4 + threads - 1) / threads;  // 65536
    int maskBlocks = D / 16;                     // 256

    bool fused_ok = (D <= 4096) && (D % 256 == 0) && ((D & (D - 1)) == 0) &&
                    (n % 4 == 0) && (blocks >= maskBlocks);

    if (fused_ok) {
        // Reset the device-side arrival counter (graph-capturable memset node).
        void* done_addr = nullptr;
        cudaGetSymbolAddress(&done_addr, g_done);
        cudaMemsetAsync(done_addr, 0, sizeof(unsigned int), 0);

        unsigned int d4_mask = (unsigned int)(D / 4) - 1u;
        fused_kernel<<<blocks, threads>>>((const float4*)x, coef,
                                          (float4*)d_out, n4, d4_mask,
                                          imp, D, keep, maskBlocks);
    } else {
        mask_kernel_fb<<<(D + 255) / 256, 256>>>(imp, D, keep);
        poly_kernel_fb<<<(n + 255) / 256, 256>>>(x, coef, (float*)d_out, n, D);
    }
}

// round 6
// speedup vs baseline: 1.0635x; 1.0635x over previous
#include <cuda_runtime.h>
#include <cuda_bf16.h>
#include <cstdint>

#define MAX_D 8192
__device__ __align__(128) float g_mask[MAX_D];

// ---------------------------------------------------------------------------
// Kernel 1: exact top-k channel mask, lax.top_k tie-breaking.
// rank(d) = #{j: imp[j] > imp[d]} + #{j < d: imp[j] == imp[d]};
// mask[d] = rank < keep.
// Grid: D/16 blocks x 256 threads; 16 channels x 16 j-slices per block.
// Triggers programmatic launch completion once g_mask is globally visible.
// Assumes D <= 4096, D % 256 == 0.
// ---------------------------------------------------------------------------
__global__ void __launch_bounds__(256)
mask_kernel(const float* __restrict__ imp, int D, int keep) {
    __shared__ float s_imp[4096];          // 16 KB
    __shared__ int   s_part[16][17];

    int tid = threadIdx.x;
    for (int j = tid; j < D; j += blockDim.x) s_imp[j] = imp[j];
    __syncthreads();

    int chIdx = tid & 15;                  // channel within block
    int sl    = tid >> 4;                  // j-slice 0..15
    int d     = blockIdx.x * 16 + chIdx;
    float v   = s_imp[d];

    int chunk = D >> 4;                    // 256 @ D=4096
    int base  = sl * chunk;
    int cnt = 0;
    #pragma unroll 8
    for (int j = 0; j < chunk; j++) {
        int jj = base + j;
        float u = s_imp[jj];
        cnt += (u > v) ? 1 : ((u == v && jj < d) ? 1 : 0);
    }
    s_part[sl][chIdx] = cnt;
    __syncthreads();

    if (tid < 16) {
        int r = 0;
        #pragma unroll
        for (int s = 0; s < 16; s++) r += s_part[s][tid];
        g_mask[blockIdx.x * 16 + tid] = (r < keep) ? 1.0f : 0.0f;
    }

    __threadfence();
    __syncthreads();
    cudaTriggerProgrammaticLaunchCompletion();
}

// ---------------------------------------------------------------------------
// Kernel 2: streaming polynomial, 2x float4 per thread, PDL overlap.
// Loads x BEFORE the grid-dependency sync; reads g_mask after.
// y = x + m*(poly(x) - x),  poly = x*(c0 + x*(c1 + x*c2))
// Assumes n4 even (n % 8 == 0).
// ---------------------------------------------------------------------------
__global__ void __launch_bounds__(256)
poly_kernel(const float4* __restrict__ x,
            const float* __restrict__ coeffs,
            float4* __restrict__ out,
            int n4, unsigned int d4_mask) {
    int i0 = (blockIdx.x * blockDim.x + threadIdx.x) * 2;
    int i1 = i0 + 1;
    bool a0 = (i0 < n4);
    bool a1 = (i1 < n4);

    // Pre-sync: both long-latency loads issued back-to-back (MLP=2).
    float4 x0 = make_float4(0.f,0.f,0.f,0.f);
    float4 x1 = make_float4(0.f,0.f,0.f,0.f);
    if (a0) x0 = x[i0];
    if (a1) x1 = x[i1];
    float c0 = __ldg(&coeffs[0]);
    float c1 = __ldg(&coeffs[1]);
    float c2 = __ldg(&coeffs[2]);

    float4 p0, p1;
    p0.x = x0.x * fmaf(x0.x, fmaf(x0.x, c2, c1), c0);
    p0.y = x0.y * fmaf(x0.y, fmaf(x0.y, c2, c1), c0);
    p0.z = x0.z * fmaf(x0.z, fmaf(x0.z, c2, c1), c0);
    p0.w = x0.w * fmaf(x0.w, fmaf(x0.w, c2, c1), c0);
    p1.x = x1.x * fmaf(x1.x, fmaf(x1.x, c2, c1), c0);
    p1.y = x1.y * fmaf(x1.y, fmaf(x1.y, c2, c1), c0);
    p1.z = x1.z * fmaf(x1.z, fmaf(x1.z, c2, c1), c0);
    p1.w = x1.w * fmaf(x1.w, fmaf(x1.w, c2, c1), c0);

    cudaGridDependencySynchronize();

    const float4* m4 = reinterpret_cast<const float4*>(g_mask);
    if (a0) {
        float4 mv = m4[i0 & d4_mask];
        float4 r;
        r.x = fmaf(mv.x, p0.x - x0.x, x0.x);
        r.y = fmaf(mv.y, p0.y - x0.y, x0.y);
        r.z = fmaf(mv.z, p0.z - x0.z, x0.z);
        r.w = fmaf(mv.w, p0.w - x0.w, x0.w);
        out[i0] = r;
    }
    if (a1) {
        float4 mv = m4[i1 & d4_mask];
        float4 r;
        r.x = fmaf(mv.x, p1.x - x1.x, x1.x);
        r.y = fmaf(mv.y, p1.y - x1.y, x1.y);
        r.z = fmaf(mv.z, p1.z - x1.z, x1.z);
        r.w = fmaf(mv.w, p1.w - x1.w, x1.w);
        out[i1] = r;
    }
}

// ---------------------------------------------------------------------------
// Fallback path (scalar, any shape).
// ---------------------------------------------------------------------------
__global__ void mask_kernel_fb(const float* __restrict__ imp, int D, int keep) {
    int d = blockIdx.x * blockDim.x + threadIdx.x;
    if (d >= D) return;
    float v = imp[d];
    int cnt = 0;
    for (int j = 0; j < D; j++) {
        float u = imp[j];
        cnt += (u > v) ? 1 : ((u == v && j < d) ? 1 : 0);
    }
    g_mask[d] = (cnt < keep) ? 1.0f : 0.0f;
}

__global__ void poly_kernel_fb(const float* __restrict__ x,
                               const float* __restrict__ coeffs,
                               float* __restrict__ out, int n, int D) {
    int i = blockIdx.x * blockDim.x + threadIdx.x;
    if (i >= n) return;
    float c0 = coeffs[0], c1 = coeffs[1], c2 = coeffs[2];
    float xv = x[i];
    float m = g_mask[i % D];
    float p = xv * fmaf(xv, fmaf(xv, c2, c1), c0);
    out[i] = fmaf(m, p - xv, xv);
}

extern "C" void kernel_launch(void* const* d_in, const int* in_sizes, int n_in,
                              void* d_out, int out_size) {
    const float* x    = (const float*)d_in[0];   // (B, T, D) fp32
    const float* coef = (const float*)d_in[1];   // (3,) fp32
    const float* imp  = (const float*)d_in[2];   // (D,) fp32

    int D    = in_sizes[2];                      // 4096
    int keep = (int)(D * 0.5);
    if (keep < 1) keep = 1;
    int n    = in_sizes[0];                      // B*T*D

    bool fast_ok = (D <= 4096) && (D % 256 == 0) && ((D & (D - 1)) == 0) &&
                   (n % 8 == 0);

    if (!fast_ok) {
        mask_kernel_fb<<<(D + 255) / 256, 256>>>(imp, D, keep);
        poly_kernel_fb<<<(n + 255) / 256, 256>>>(x, coef, (float*)d_out, n, D);
        return;
    }

    // Kernel 1: exact-rank mask (16 KB smem, D/16 blocks).
    mask_kernel<<<D / 16, 256>>>(imp, D, keep);

    // Kernel 2: streaming poly with PDL overlap, 2 float4 / thread.
    {
        int n4 = n / 4;
        unsigned int d4_mask = (unsigned int)(D / 4) - 1u;
        int threads = 256;
        int blocks  = (n4 / 2 + threads - 1) / threads;   // 32768

        cudaLaunchAttribute attrs[1];
        attrs[0].id = cudaLaunchAttributeProgrammaticStreamSerialization;
        attrs[0].val.programmaticStreamSerializationAllowed = 1;

        cudaLaunchConfig_t cfg = {};
        cfg.gridDim  = dim3((unsigned)blocks, 1, 1);
        cfg.blockDim = dim3((unsigned)threads, 1, 1);
        cfg.dynamicSmemBytes = 0;
        cfg.stream   = 0;
        cfg.attrs    = attrs;
        cfg.numAttrs = 1;

        cudaError_t err = cudaLaunchKernelEx(&cfg, poly_kernel,
                                             (const float4*)x, coef,
                                             (float4*)d_out, n4, d4_mask);
        if (err != cudaSuccess) {
            poly_kernel<<<blocks, threads>>>((const float4*)x, coef,
                                             (float4*)d_out, n4, d4_mask);
        }
    }
}

// round 10
// speedup vs baseline: 1.1067x; 1.0406x over previous
#include <cuda_runtime.h>
#include <cuda_bf16.h>
#include <cstdint>

#define MAX_D 8192
__device__ __align__(128) float g_mask[MAX_D];

// ---------------------------------------------------------------------------
// Kernel 1: exact top-k channel mask, lax.top_k tie-breaking.
// rank(d) = #{j: imp[j] > imp[d]} + #{j < d: imp[j] == imp[d]}; mask = rank<keep.
// Grid: D/16 blocks x 256 threads. Assumes D <= 4096, D % 256 == 0.
// ---------------------------------------------------------------------------
__global__ void __launch_bounds__(256)
mask_kernel(const float* __restrict__ imp, int D, int keep) {
    __shared__ float s_imp[4096];          // 16 KB
    __shared__ int   s_part[16][17];

    int tid = threadIdx.x;
    for (int j = tid; j < D; j += blockDim.x) s_imp[j] = imp[j];
    __syncthreads();

    int chIdx = tid & 15;
    int sl    = tid >> 4;
    int d     = blockIdx.x * 16 + chIdx;
    float v   = s_imp[d];

    int chunk = D >> 4;
    int base  = sl * chunk;
    int cnt = 0;
    #pragma unroll 8
    for (int j = 0; j < chunk; j++) {
        int jj = base + j;
        float u = s_imp[jj];
        cnt += (u > v) ? 1 : ((u == v && jj < d) ? 1 : 0);
    }
    s_part[sl][chIdx] = cnt;
    __syncthreads();

    if (tid < 16) {
        int r = 0;
        #pragma unroll
        for (int s = 0; s < 16; s++) r += s_part[s][tid];
        g_mask[blockIdx.x * 16 + tid] = (r < keep) ? 1.0f : 0.0f;
    }

    __threadfence();
    __syncthreads();
    cudaTriggerProgrammaticLaunchCompletion();
}

// ---------------------------------------------------------------------------
// Kernel 2: streaming polynomial, 4x float4 per thread, BLOCK-STRIDED
// (i_k = bid*1024 + tid + k*256 -> every LDG/STG fully coalesced, MLP_p1=4).
// Loads issued before the grid-dependency sync (PDL overlap with mask).
// y = x + m*(poly(x) - x),  poly = x*(c0 + x*(c1 + x*c2))
// ---------------------------------------------------------------------------
__global__ void __launch_bounds__(256)
poly_kernel(const float4* __restrict__ x,
            const float* __restrict__ coeffs,
            float4* __restrict__ out,
            int n4, unsigned int d4_mask) {
    int base = blockIdx.x * 1024 + threadIdx.x;

    int  idx[4];
    bool act[4];
    #pragma unroll
    for (int k = 0; k < 4; k++) {
        idx[k] = base + k * 256;
        act[k] = (idx[k] < n4);
    }

    // Pre-sync: 4 coalesced streaming loads, front-batched.
    float4 xv[4];
    #pragma unroll
    for (int k = 0; k < 4; k++)
        xv[k] = act[k] ? __ldcs(&x[idx[k]]) : make_float4(0.f, 0.f, 0.f, 0.f);

    float c0 = __ldg(&coeffs[0]);
    float c1 = __ldg(&coeffs[1]);
    float c2 = __ldg(&coeffs[2]);

    float4 p[4];
    #pragma unroll
    for (int k = 0; k < 4; k++) {
        p[k].x = xv[k].x * fmaf(xv[k].x, fmaf(xv[k].x, c2, c1), c0);
        p[k].y = xv[k].y * fmaf(xv[k].y, fmaf(xv[k].y, c2, c1), c0);
        p[k].z = xv[k].z * fmaf(xv[k].z, fmaf(xv[k].z, c2, c1), c0);
        p[k].w = xv[k].w * fmaf(xv[k].w, fmaf(xv[k].w, c2, c1), c0);
    }

    cudaGridDependencySynchronize();

    const float4* m4 = reinterpret_cast<const float4*>(g_mask);
    #pragma unroll
    for (int k = 0; k < 4; k++) {
        if (act[k]) {
            float4 mv = m4[idx[k] & d4_mask];
            float4 r;
            r.x = fmaf(mv.x, p[k].x - xv[k].x, xv[k].x);
            r.y = fmaf(mv.y, p[k].y - xv[k].y, xv[k].y);
            r.z = fmaf(mv.z, p[k].z - xv[k].z, xv[k].z);
            r.w = fmaf(mv.w, p[k].w - xv[k].w, xv[k].w);
            __stcs(&out[idx[k]], r);
        }
    }
}

// ---------------------------------------------------------------------------
// Fallback path (scalar, any shape).
// ---------------------------------------------------------------------------
__global__ void mask_kernel_fb(const float* __restrict__ imp, int D, int keep) {
    int d = blockIdx.x * blockDim.x + threadIdx.x;
    if (d >= D) return;
    float v = imp[d];
    int cnt = 0;
    for (int j = 0; j < D; j++) {
        float u = imp[j];
        cnt += (u > v) ? 1 : ((u == v && j < d) ? 1 : 0);
    }
    g_mask[d] = (cnt < keep) ? 1.0f : 0.0f;
}

__global__ void poly_kernel_fb(const float* __restrict__ x,
                               const float* __restrict__ coeffs,
                               float* __restrict__ out, int n, int D) {
    int i = blockIdx.x * blockDim.x + threadIdx.x;
    if (i >= n) return;
    float c0 = coeffs[0], c1 = coeffs[1], c2 = coeffs[2];
    float xv = x[i];
    float m = g_mask[i % D];
    float p = xv * fmaf(xv, fmaf(xv, c2, c1), c0);
    out[i] = fmaf(m, p - xv, xv);
}

extern "C" void kernel_launch(void* const* d_in, const int* in_sizes, int n_in,
                              void* d_out, int out_size) {
    const float* x    = (const float*)d_in[0];   // (B, T, D) fp32
    const float* coef = (const float*)d_in[1];   // (3,) fp32
    const float* imp  = (const float*)d_in[2];   // (D,) fp32

    int D    = in_sizes[2];                      // 4096
    int keep = (int)(D * 0.5);
    if (keep < 1) keep = 1;
    int n    = in_sizes[0];                      // B*T*D

    bool fast_ok = (D <= 4096) && (D % 256 == 0) && ((D & (D - 1)) == 0) &&
                   (n % 4 == 0);

    if (!fast_ok) {
        mask_kernel_fb<<<(D + 255) / 256, 256>>>(imp, D, keep);
        poly_kernel_fb<<<(n + 255) / 256, 256>>>(x, coef, (float*)d_out, n, D);
        return;
    }

    // Kernel 1: exact-rank mask.
    mask_kernel<<<D / 16, 256>>>(imp, D, keep);

    // Kernel 2: streaming poly (4 float4/thread, block-strided) with PDL.
    {
        int n4 = n / 4;
        unsigned int d4_mask = (unsigned int)(D / 4) - 1u;
        int threads = 256;
        int blocks  = (n4 + 1023) / 1024;        // 16384 @ n=64M

        cudaLaunchAttribute attrs[1];
        attrs[0].id = cudaLaunchAttributeProgrammaticStreamSerialization;
        attrs[0].val.programmaticStreamSerializationAllowed = 1;

        cudaLaunchConfig_t cfg = {};
        cfg.gridDim  = dim3((unsigned)blocks, 1, 1);
        cfg.blockDim = dim3((unsigned)threads, 1, 1);
        cfg.dynamicSmemBytes = 0;
        cfg.stream   = 0;
        cfg.attrs    = attrs;
        cfg.numAttrs = 1;

        cudaError_t err = cudaLaunchKernelEx(&cfg, poly_kernel,
                                             (const float4*)x, coef,
                                             (float4*)d_out, n4, d4_mask);
        if (err != cudaSuccess) {
            poly_kernel<<<blocks, threads>>>((const float4*)x, coef,
                                             (float4*)d_out, n4, d4_mask);
        }
    }
}